// round 6
// baseline (speedup 1.0000x reference)
#include <cuda_runtime.h>
#include <cstdint>

#define NB    16
#define NPTS  65536
#define NSEED 40
#define RAD2  0.0025f

#define FPS_CL 8
#define FPS_T  256
#define FPS_PT 32                // NPTS / (FPS_CL * FPS_T)
#define FPS_PR (FPS_PT / 2)
#define NW     (FPS_T / 32)      // 8 warps

__device__ float g_den[NB * NSEED];

// ---------------- f32x2 packed helpers (element-wise rn => bitwise == scalar)
__device__ __forceinline__ uint64_t pack2(float lo, float hi) {
    uint64_t r; asm("mov.b64 %0, {%1, %2};" : "=l"(r) : "f"(lo), "f"(hi)); return r;
}
__device__ __forceinline__ void unpack2(uint64_t v, float& lo, float& hi) {
    asm("mov.b64 {%0, %1}, %2;" : "=f"(lo), "=f"(hi) : "l"(v));
}
__device__ __forceinline__ uint64_t add2(uint64_t a, uint64_t b) {
    uint64_t r; asm("add.rn.f32x2 %0, %1, %2;" : "=l"(r) : "l"(a), "l"(b)); return r;
}
__device__ __forceinline__ uint64_t mul2(uint64_t a, uint64_t b) {
    uint64_t r; asm("mul.rn.f32x2 %0, %1, %2;" : "=l"(r) : "l"(a), "l"(b)); return r;
}
__device__ __forceinline__ uint64_t fma2(uint64_t a, uint64_t b, uint64_t c) {
    uint64_t r; asm("fma.rn.f32x2 %0, %1, %2, %3;" : "=l"(r) : "l"(a), "l"(b), "l"(c)); return r;
}

// ---------------- cluster / sync helpers
__device__ __forceinline__ uint32_t ctarank() {
    uint32_t r; asm("mov.u32 %0, %%cluster_ctarank;" : "=r"(r)); return r;
}
__device__ __forceinline__ uint32_t mapa_u32(uint32_t sa, uint32_t rank) {
    uint32_t r; asm("mapa.shared::cluster.u32 %0, %1, %2;" : "=r"(r) : "r"(sa), "r"(rank));
    return r;
}
__device__ __forceinline__ void sts_relaxed_b64(uint32_t a, uint64_t v) {
    asm volatile("st.relaxed.cta.shared::cta.b64 [%0], %1;" :: "r"(a), "l"(v) : "memory");
}
__device__ __forceinline__ void sts_release_cta_b32(uint32_t a, uint32_t v) {
    asm volatile("st.release.cta.shared::cta.b32 [%0], %1;" :: "r"(a), "r"(v) : "memory");
}
__device__ __forceinline__ uint32_t lds_acquire_cta_b32(uint32_t a) {
    uint32_t v;
    asm volatile("ld.acquire.cta.shared::cta.b32 %0, [%1];" : "=r"(v) : "r"(a) : "memory");
    return v;
}
__device__ __forceinline__ uint32_t lds_acquire_cluster_b32(uint32_t a) {
    uint32_t v;
    asm volatile("ld.acquire.cluster.shared::cta.b32 %0, [%1];" : "=r"(v) : "r"(a) : "memory");
    return v;
}
__device__ __forceinline__ uint64_t lds_b64(uint32_t a) {
    uint64_t v;
    asm volatile("ld.shared.b64 %0, [%1];" : "=l"(v) : "r"(a) : "memory");
    return v;
}
__device__ __forceinline__ void st_cluster_relaxed_b64(uint32_t a, uint64_t v) {
    asm volatile("st.relaxed.cluster.shared::cluster.b64 [%0], %1;"
                 :: "r"(a), "l"(v) : "memory");
}
__device__ __forceinline__ void st_cluster_relaxed_b32(uint32_t a, uint32_t v) {
    asm volatile("st.relaxed.cluster.shared::cluster.b32 [%0], %1;"
                 :: "r"(a), "r"(v) : "memory");
}
__device__ __forceinline__ void st_cluster_release_b32(uint32_t a, uint32_t v) {
    asm volatile("st.release.cluster.shared::cluster.b32 [%0], %1;"
                 :: "r"(a), "r"(v) : "memory");
}
__device__ __forceinline__ void cluster_sync_all() {
    asm volatile("barrier.cluster.arrive.aligned;" ::: "memory");
    asm volatile("barrier.cluster.wait.aligned;" ::: "memory");
}

// ---------------------------------------------------------------------------
// Kernel 1: FPS + density, fused. 8-CTA cluster per batch, 256 thr/CTA,
// 32 pts/thread register-resident. NO barriers / mbarriers inside the step
// loop: all hand-offs are monotonic step tags (k+1) with release stores and
// local acquire spin-loops.
//   warp: scan -> REDUX max dist, REDUX min first-gi -> lane0 publishes
//         {key, tag=k+1} to s_wkey[w]/s_wtag[w]            (st.release.cta)
//   warp0: lanes<8 spin on s_wtag==k+1, dual REDUX -> CTA key; lane0 stores
//         {key, tag} into rank0's rx slot                  (st.release.cluster)
//   rank0 warp0: lanes<8 spin on local rx tags, dual REDUX -> winner gi;
//         lane0 LDGs winner xyz; lanes<8 store {xy, z, tag} into EVERY CTA's
//         s_seeds[k+1] + s_seedtag                         (st.release.cluster)
//   all warps: spin on local s_seedtag==k+1 -> next step.
// WAR safety: slot for step k+1 is rewritten only after the writer has
// consumed the step-k broadcast, which happens only after the reader consumed
// the step-k slot (consume-before-produce chain); tags disambiguate.
// Tie-break: key {distbits<<32 | ~gi}, max => max dist then FIRST index, ==
// jnp.argmax. Distance math: rn mul/add in reference order, bitexact.
// ---------------------------------------------------------------------------
__global__ void __cluster_dims__(FPS_CL, 1, 1) __launch_bounds__(FPS_T, 1)
fps_kernel(const float* __restrict__ pcs)
{
    const uint32_t rank = ctarank();
    const int batch = blockIdx.x / FPS_CL;
    const int t = threadIdx.x;
    const int lane = t & 31;
    const int warp = t >> 5;

    __shared__ __align__(16) float s_seeds[NSEED][4];
    __shared__ uint32_t s_seedtag;
    __shared__ __align__(8) uint64_t s_wkey[NW];
    __shared__ uint32_t s_wtag[NW];
    __shared__ __align__(8) uint64_t s_rxkey[FPS_CL];
    __shared__ uint32_t s_rxtag[FPS_CL];
    __shared__ float s_part[NSEED][FPS_T + 1];

    const float* base = pcs + (size_t)batch * NPTS * 3;
    const int gi0 = (int)rank * (FPS_T * FPS_PT) + t;

    // ---- load 32 points, pack pairs (2j, 2j+1)
    uint64_t PX[FPS_PR], PY[FPS_PR], PZ[FPS_PR];
#pragma unroll
    for (int j = 0; j < FPS_PR; j++) {
        const int ga = gi0 + (2 * j) * FPS_T;
        const int gb = gi0 + (2 * j + 1) * FPS_T;
        PX[j] = pack2(base[ga * 3 + 0], base[gb * 3 + 0]);
        PY[j] = pack2(base[ga * 3 + 1], base[gb * 3 + 1]);
        PZ[j] = pack2(base[ga * 3 + 2], base[gb * 3 + 2]);
    }
    unsigned db[FPS_PT];
#pragma unroll
    for (int i = 0; i < FPS_PT; i++) db[i] = __float_as_uint(1e10f);

    if (t == 0) s_seedtag = 0;
    if (t < NW) s_wtag[t] = 0;
    if (t < FPS_CL) s_rxtag[t] = 0;
    if (t < 3) s_seeds[0][t] = base[t];
    if (rank == 0 && t < NSEED) g_den[batch * NSEED + t] = 0.0f;
    __syncthreads();
    cluster_sync_all();   // all tags zeroed cluster-wide before any traffic

    const uint32_t a_seedtag = (uint32_t)__cvta_generic_to_shared(&s_seedtag);
    const uint32_t a_seeds   = (uint32_t)__cvta_generic_to_shared(&s_seeds[0][0]);

    // =================== FPS main loop (no barriers) ===================
#pragma unroll 1
    for (int k = 0; k < NSEED - 1; k++) {
        const uint32_t tag = (uint32_t)(k + 1);
        const float cx = s_seeds[k][0], cy = s_seeds[k][1], cz = s_seeds[k][2];
        const uint64_t ncx2 = pack2(-cx, -cx);
        const uint64_t ncy2 = pack2(-cy, -cy);
        const uint64_t ncz2 = pack2(-cz, -cz);

        // ---- packed scan, dual max accumulators
        unsigned bd0 = 0, bd1 = 0;
#pragma unroll
        for (int j = 0; j < FPS_PR; j++) {
            const uint64_t ax = add2(PX[j], ncx2);
            const uint64_t ay = add2(PY[j], ncy2);
            const uint64_t az = add2(PZ[j], ncz2);
            const uint64_t dd = add2(add2(mul2(ax, ax), mul2(ay, ay)), mul2(az, az));
            float f0, f1; unpack2(dd, f0, f1);
            db[2 * j]     = min(db[2 * j],     __float_as_uint(f0));
            db[2 * j + 1] = min(db[2 * j + 1], __float_as_uint(f1));
            bd0 = max(bd0, db[2 * j]);
            bd1 = max(bd1, db[2 * j + 1]);
        }
        const unsigned bd = max(bd0, bd1);

        // ---- warp reduce: max dist, then first (min) gi among candidates
        const unsigned wbd = __reduce_max_sync(0xffffffffu, bd);
        unsigned mygi = 0xffffffffu;
        if (bd == wbd) {
#pragma unroll
            for (int i = 0; i < FPS_PT; i++)
                if (db[i] == wbd) mygi = min(mygi, (unsigned)(gi0 + i * FPS_T));
        }
        const unsigned wgi = __reduce_min_sync(0xffffffffu, mygi);
        if (lane == 0) {
            const uint64_t key = ((uint64_t)wbd << 32) | (unsigned)(~wgi);
            sts_relaxed_b64((uint32_t)__cvta_generic_to_shared(&s_wkey[warp]), key);
            sts_release_cta_b32((uint32_t)__cvta_generic_to_shared(&s_wtag[warp]), tag);
        }

        if (warp == 0) {
            // ---- gather 8 warp keys (local spin), dual REDUX
            uint64_t kk = 0;
            if (lane < NW) {
                const uint32_t a_tag =
                    (uint32_t)__cvta_generic_to_shared(&s_wtag[lane]);
                while (lds_acquire_cta_b32(a_tag) != tag) {}
                kk = lds_b64((uint32_t)__cvta_generic_to_shared(&s_wkey[lane]));
            }
            const unsigned khi = (unsigned)(kk >> 32);
            const unsigned klo = (unsigned)kk;
            const unsigned hi = __reduce_max_sync(0xffffffffu, khi);
            const unsigned lo = __reduce_max_sync(0xffffffffu, (khi == hi) ? klo : 0u);
            const uint64_t ckey = ((uint64_t)hi << 32) | lo;

            // ---- send CTA key to rank0's rx slot
            if (lane == 0) {
                const uint32_t rk_loc =
                    (uint32_t)__cvta_generic_to_shared(&s_rxkey[rank]);
                const uint32_t rt_loc =
                    (uint32_t)__cvta_generic_to_shared(&s_rxtag[rank]);
                st_cluster_relaxed_b64(mapa_u32(rk_loc, 0), ckey);
                st_cluster_release_b32(mapa_u32(rt_loc, 0), tag);
            }

            // ---- rank0: aggregate 8 CTA keys, fetch winner xyz, broadcast
            if (rank == 0) {
                uint64_t sk = 0;
                if (lane < FPS_CL) {
                    const uint32_t a_tag =
                        (uint32_t)__cvta_generic_to_shared(&s_rxtag[lane]);
                    while (lds_acquire_cluster_b32(a_tag) != tag) {}
                    sk = lds_b64((uint32_t)__cvta_generic_to_shared(&s_rxkey[lane]));
                }
                const unsigned shi = (unsigned)(sk >> 32);
                const unsigned slo = (unsigned)sk;
                const unsigned hi2 = __reduce_max_sync(0xffffffffu, shi);
                const unsigned lo2 =
                    __reduce_max_sync(0xffffffffu, (shi == hi2) ? slo : 0u);
                const unsigned widx = ~lo2;

                float wx = 0.f, wy = 0.f, wz = 0.f;
                if (lane == 0) {
                    const float* wp = base + (size_t)widx * 3;
                    wx = wp[0]; wy = wp[1]; wz = wp[2];
                }
                wx = __shfl_sync(0xffffffffu, wx, 0);
                wy = __shfl_sync(0xffffffffu, wy, 0);
                wz = __shfl_sync(0xffffffffu, wz, 0);

                if (lane < FPS_CL) {
                    const uint32_t dst = a_seeds + (uint32_t)(k + 1) * 16;
                    st_cluster_relaxed_b64(mapa_u32(dst, (uint32_t)lane),
                                           pack2(wx, wy));
                    st_cluster_relaxed_b32(mapa_u32(dst + 8, (uint32_t)lane),
                                           __float_as_uint(wz));
                    st_cluster_release_b32(mapa_u32(a_seedtag, (uint32_t)lane), tag);
                }
            }
        }

        // ---- everyone: wait for the new seed (local spin on one word)
        while (lds_acquire_cluster_b32(a_seedtag) != tag) {}
    }

    // =================== density tail ===================
    const uint64_t signmask = 0x8000000080000000ull;
    uint64_t NPN[FPS_PR];
#pragma unroll
    for (int j = 0; j < FPS_PR; j++) {
        const uint64_t pn =
            add2(add2(mul2(PX[j], PX[j]), mul2(PY[j], PY[j])), mul2(PZ[j], PZ[j]));
        NPN[j] = pn ^ signmask;
    }

#pragma unroll 1
    for (int s = 0; s < NSEED; s++) {
        const float sx = s_seeds[s][0], sy = s_seeds[s][1], sz = s_seeds[s][2];
        const float qw = RAD2 - (sx * sx + sy * sy + sz * sz);
        const uint64_t qx2 = pack2(2.0f * sx, 2.0f * sx);
        const uint64_t qy2 = pack2(2.0f * sy, 2.0f * sy);
        const uint64_t qz2 = pack2(2.0f * sz, 2.0f * sz);
        const uint64_t qw2 = pack2(qw, qw);
        float acc = 0.0f;
#pragma unroll
        for (int j = 0; j < FPS_PR; j++) {
            uint64_t v = add2(qw2, NPN[j]);
            v = fma2(PX[j], qx2, v);
            v = fma2(PY[j], qy2, v);
            v = fma2(PZ[j], qz2, v);
            float v0, v1; unpack2(v, v0, v1);
            acc += fmaxf(v0, 0.0f);
            acc += fmaxf(v1, 0.0f);
        }
        s_part[s][t] = acc;
    }
    __syncthreads();

    if (t < NSEED) {
        const float* row = &s_part[t][0];
        float a0 = 0.f, a1 = 0.f, a2 = 0.f, a3 = 0.f;
#pragma unroll 4
        for (int i = 0; i < FPS_T; i += 4) {
            a0 += row[i]; a1 += row[i + 1]; a2 += row[i + 2]; a3 += row[i + 3];
        }
        atomicAdd(&g_den[batch * NSEED + t], (a0 + a1) + (a2 + a3));
    }
}

// ---------------------------------------------------------------------------
// Kernel 2: out = mean_b( var_{ddof=1,s}( den[b][s] ) )
// ---------------------------------------------------------------------------
__global__ void var_kernel(float* __restrict__ out)
{
    const int lane = threadIdx.x;
    float v = 0.0f;
    if (lane < NB) {
        const float* d = &g_den[lane * NSEED];
        float s = 0.0f;
        for (int i = 0; i < NSEED; i++) s += d[i];
        const float m = s * (1.0f / NSEED);
        float q = 0.0f;
        for (int i = 0; i < NSEED; i++) {
            const float e = d[i] - m;
            q += e * e;
        }
        v = q * (1.0f / (NSEED - 1));
    }
#pragma unroll
    for (int off = 8; off; off >>= 1)
        v += __shfl_down_sync(0xffffffffu, v, off);
    if (lane == 0) out[0] = v * (1.0f / NB);
}

// ---------------------------------------------------------------------------
extern "C" void kernel_launch(void* const* d_in, const int* in_sizes, int n_in,
                              void* d_out, int out_size)
{
    const float* pcs = (const float*)d_in[0];
    (void)in_sizes; (void)n_in; (void)out_size;

    fps_kernel<<<NB * FPS_CL, FPS_T>>>(pcs);
    var_kernel<<<1, 32>>>((float*)d_out);
}